// round 4
// baseline (speedup 1.0000x reference)
#include <cuda_runtime.h>
#include <math.h>

// pyGAMNet on GB300.
// Cols 0..47: per-feature scalar MLP 1->40->20->1 (ReLU)  == piecewise-linear f(x).
// Cols 48..63: class_bias[c, (int)x] gather.
//
// R4: collapse MLP to exact PWL (validated in R3), then sample it into a
// 16384-bucket chord table over [-6,6]. Eval = 1 LDG.64 + 3 fma. Exact
// binary-search fallback for |x|>6 (~never taken).

#define BSZ   131072
#define NCOL  64
#define NF    48
#define H0N   40
#define H1N   20
#define PADN  1024            // padded PWL table (max segments 861)

#define NB    16384
#define XMIN  (-6.0f)
#define XMAX  (6.0f)
#define WB    (12.0f / 16384.0f)      // 3/4096, exact in fp32
#define SCALE (16384.0f / 12.0f)
#define INVW  (16384.0f / 12.0f)

#define TPB   256
#define RPT   4
#define ROWS_BLK (TPB * RPT)  // 1024 rows per eval block

#define F_INF  __int_as_float(0x7f800000)

__device__ float  g_bp[NF][PADN];    // sorted breakpoints, +INF padded (tail fallback)
__device__ float2 g_AC[NF][PADN];    // per-segment (A, C): f = A*x + C
__device__ float2 g_tab[NF][NB];     // per bucket: (y_left, chord_slope)

// ---------------------------------------------------------------------------
// Precompute scratch layout (dynamic smem)
// ---------------------------------------------------------------------------
struct PreScr {
    float sw0[H0N], sb0[H0N], sthr[H0N], ssthr[H0N];
    int   ssidx[H0N];
    float sW1[H0N * H1N];
    float sb1[H1N], sw2[H1N], sb2;
    float sak[41][H1N], sck[41][H1N];
    float crossZ[41][H1N];
    int   crossK[41][H1N];
    int   cnt[41], offs[42];
};

#define SB_OFF   0
#define SAC_OFF  4096
#define YV_OFF   12288
#define SCR_OFF  77832                       // 12288 + 16385*4 = 77828 -> align 8
#define SMEM_PRE (SCR_OFF + sizeof(PreScr))  // ~95.5 KB

// ---------------------------------------------------------------------------
// Precompute: one block (256 thr) per feature. Phase A: exact PWL (as R3).
// Phase B: sample f at 16385 grid points, emit chord table.
// ---------------------------------------------------------------------------
__global__ __launch_bounds__(256) void gam_precompute_kernel(
    const float* __restrict__ W0, const float* __restrict__ b0,
    const float* __restrict__ W1, const float* __restrict__ b1,
    const float* __restrict__ W2, const float* __restrict__ b2)
{
    extern __shared__ char smem[];
    float*  sB  = (float*)(smem + SB_OFF);     // [PADN]
    float2* sAC = (float2*)(smem + SAC_OFF);   // [PADN]
    float*  yv  = (float*)(smem + YV_OFF);     // [NB+1]
    PreScr* S   = (PreScr*)(smem + SCR_OFF);

    const int n = blockIdx.x;
    const int t = threadIdx.x;

    // ---- Phase A: exact PWL collapse (validated R3 logic) ----
    for (int i = t; i < H0N * H1N; i += 256) S->sW1[i] = W1[n * H0N * H1N + i];
    if (t < H0N) {
        float w = W0[n * H0N + t];
        float b = b0[n * H0N + t];
        S->sw0[t] = w; S->sb0[t] = b;
        S->sthr[t] = (w != 0.0f) ? (-b / w) : ((b > 0.0f) ? -F_INF : F_INF);
    }
    if (t >= 64 && t < 64 + H1N) S->sb1[t - 64] = b1[n * H1N + (t - 64)];
    if (t >= 96 && t < 96 + H1N) S->sw2[t - 96] = W2[n * H1N + (t - 96)];
    if (t == 128) S->sb2 = b2[n];
    __syncthreads();

    if (t < H0N) {   // stable rank-sort of thresholds
        float v = S->sthr[t];
        int r = 0;
        for (int m = 0; m < H0N; m++) {
            float u = S->sthr[m];
            r += (u < v) || (u == v && m < t);
        }
        S->ssthr[r] = v;
        S->ssidx[r] = t;
    }
    __syncthreads();

    for (int idx = t; idx < 41 * H1N; idx += 256) {   // collapsed lines per interval
        const int i = idx / H1N;
        const int k = idx % H1N;
        float a = 0.0f, c = S->sb1[k];
        for (int r = 0; r < H0N; r++) {
            const int j = S->ssidx[r];
            const float w0 = S->sw0[j];
            const bool act = (w0 < 0.0f) ? (r >= i) : (r < i);
            if (act) {
                const float w1v = S->sW1[j * H1N + k];
                a = fmaf(w1v, w0, a);
                c = fmaf(w1v, S->sb0[j], c);
            }
        }
        S->sak[i][k] = a;
        S->sck[i][k] = c;
    }
    __syncthreads();

    if (t < 41) {    // interior zero crossings, sorted
        const int i = t;
        const float lo = (i == 0)  ? -F_INF : S->ssthr[i - 1];
        const float hi = (i == 40) ?  F_INF : S->ssthr[i];
        int c = 0;
        for (int k = 0; k < H1N; k++) {
            const float a = S->sak[i][k];
            if (a != 0.0f) {
                const float z = -S->sck[i][k] / a;
                if (z > lo && z < hi) {
                    int p = c++;
                    while (p > 0 && S->crossZ[i][p - 1] > z) {
                        S->crossZ[i][p] = S->crossZ[i][p - 1];
                        S->crossK[i][p] = S->crossK[i][p - 1];
                        p--;
                    }
                    S->crossZ[i][p] = z;
                    S->crossK[i][p] = k;
                }
            }
        }
        S->cnt[i] = c;
    }
    __syncthreads();

    if (t == 0) {
        int s = 0;
        for (int i = 0; i < 41; i++) { S->offs[i] = s; s += S->cnt[i] + 1; }
        S->offs[41] = s;
    }
    __syncthreads();
    const int total = S->offs[41];

    if (t < 41) {    // emit segments into smem
        const int i = t;
        const float lo = (i == 0) ? -F_INF : S->ssthr[i - 1];
        unsigned actm = 0;
        float A = 0.0f, C = S->sb2;
        for (int k = 0; k < H1N; k++) {
            const float a = S->sak[i][k], cc = S->sck[i][k];
            bool av;
            if (a == 0.0f)      av = (cc > 0.0f);
            else if (i == 0)    av = (a < 0.0f);
            else {
                const float v = fmaf(a, lo, cc);
                av = (v > 0.0f) || (v == 0.0f && a > 0.0f);
            }
            if (av) {
                actm |= (1u << k);
                A = fmaf(S->sw2[k], a,  A);
                C = fmaf(S->sw2[k], cc, C);
            }
        }
        const int base = S->offs[i];
        sAC[base] = make_float2(A, C);
        for (int s = 0; s < S->cnt[i]; s++) {
            sB[base + s] = S->crossZ[i][s];
            const int k = S->crossK[i][s];
            const float sgn = (actm >> k) & 1u ? -1.0f : 1.0f;
            actm ^= (1u << k);
            A = fmaf(sgn * S->sw2[k], S->sak[i][k], A);
            C = fmaf(sgn * S->sw2[k], S->sck[i][k], C);
            sAC[base + s + 1] = make_float2(A, C);
        }
        if (i < 40) sB[base + S->cnt[i]] = S->ssthr[i];
    }
    __syncthreads();

    for (int j = total - 1 + t; j < PADN; j += 256) sB[j] = F_INF;
    __syncthreads();

    // export exact PWL for the tail fallback
    for (int j = t; j < PADN; j += 256) {
        g_bp[n][j] = sB[j];
        g_AC[n][j] = (j < total) ? sAC[j] : make_float2(0.0f, 0.0f);
    }

    // ---- Phase B: sample f at NB+1 grid points (segment marching) ----
    {
        const int per = (NB + 1 + 255) / 256;   // 65 points per thread
        const int i0 = t * per;
        const int i1 = min(i0 + per, NB + 1);
        if (i0 < i1) {
            float x0 = fmaf((float)i0, WB, XMIN);
            int p = 0;
            #pragma unroll
            for (int s = 512; s >= 1; s >>= 1)
                if (sB[p + s - 1] < x0) p += s;
            for (int i = i0; i < i1; i++) {
                const float x = fmaf((float)i, WB, XMIN);
                while (sB[p] < x) p++;
                const float2 ac = sAC[p];
                yv[i] = fmaf(ac.x, x, ac.y);
            }
        }
    }
    __syncthreads();

    // chord table: (y_left, chord slope)
    for (int b = t; b < NB; b += 256)
        g_tab[n][b] = make_float2(yv[b], (yv[b + 1] - yv[b]) * INVW);
}

// ---------------------------------------------------------------------------
// Eval (fused num + cat). Block = 1024 rows x 4 columns.
// ---------------------------------------------------------------------------
__global__ __launch_bounds__(TPB) void gam_eval_kernel(
    const float* __restrict__ in,
    const float* __restrict__ cb,
    float* __restrict__ out)
{
    const int g   = blockIdx.y;
    const int tid = threadIdx.x;
    const int rbase = blockIdx.x * ROWS_BLK + tid;

    if (g < 12) {
        #pragma unroll
        for (int e = 0; e < RPT; e++) {
            const int row = rbase + e * TPB;
            const float4 v = *reinterpret_cast<const float4*>(in + row * NCOL + g * 4);
            const float xs[4] = {v.x, v.y, v.z, v.w};
            float os[4];
            #pragma unroll
            for (int f = 0; f < 4; f++) {
                const int n = g * 4 + f;
                const float x = xs[f];
                float r;
                if (x >= XMIN && x <= XMAX) {
                    int b = (int)((x - XMIN) * SCALE);
                    b = min(b, NB - 1);
                    const float2 ys = __ldg(&g_tab[n][b]);
                    const float xL = fmaf((float)b, WB, XMIN);
                    r = fmaf(ys.y, x - xL, ys.x);
                } else {
                    // exact PWL fallback (|x| > 6: ~never)
                    int p = 0;
                    #pragma unroll
                    for (int s = 512; s >= 1; s >>= 1)
                        if (g_bp[n][p + s - 1] < x) p += s;
                    const float2 ac = g_AC[n][p];
                    r = fmaf(ac.x, x, ac.y);
                }
                os[f] = r;
            }
            *reinterpret_cast<float4*>(out + row * NCOL + g * 4) =
                make_float4(os[0], os[1], os[2], os[3]);
        }
    } else {
        __shared__ float scb[16 * 32];
        for (int i = tid; i < 16 * 32; i += TPB) scb[i] = cb[i];
        __syncthreads();

        const int cbase = (g - 12) * 4;
        #pragma unroll
        for (int e = 0; e < RPT; e++) {
            const int row = rbase + e * TPB;
            const float4 v = *reinterpret_cast<const float4*>(in + row * NCOL + g * 4);
            float4 o;
            o.x = scb[(cbase + 0) * 32 + (int)v.x];
            o.y = scb[(cbase + 1) * 32 + (int)v.y];
            o.z = scb[(cbase + 2) * 32 + (int)v.z];
            o.w = scb[(cbase + 3) * 32 + (int)v.w];
            *reinterpret_cast<float4*>(out + row * NCOL + g * 4) = o;
        }
    }
}

extern "C" void kernel_launch(void* const* d_in, const int* in_sizes, int n_in,
                              void* d_out, int out_size)
{
    const float* in = (const float*)d_in[0];
    const float* W0 = (const float*)d_in[1];
    const float* b0 = (const float*)d_in[2];
    const float* W1 = (const float*)d_in[3];
    const float* b1 = (const float*)d_in[4];
    const float* W2 = (const float*)d_in[5];
    const float* b2 = (const float*)d_in[6];
    const float* cb = (const float*)d_in[7];
    float* out = (float*)d_out;

    static bool attr_done = false;
    if (!attr_done) {
        cudaFuncSetAttribute(gam_precompute_kernel,
                             cudaFuncAttributeMaxDynamicSharedMemorySize,
                             (int)SMEM_PRE);
        attr_done = true;
    }

    gam_precompute_kernel<<<NF, 256, SMEM_PRE>>>(W0, b0, W1, b1, W2, b2);

    dim3 grid(BSZ / ROWS_BLK, 16, 1);   // 128 x 16
    gam_eval_kernel<<<grid, TPB>>>(in, cb, out);
}

// round 5
// speedup vs baseline: 1.1828x; 1.1828x over previous
#include <cuda_runtime.h>
#include <math.h>

// pyGAMNet on GB300.
// Cols 0..47: per-feature scalar MLP 1->40->20->1 (ReLU)  == piecewise-linear f(x).
// Cols 48..63: class_bias[c, (int)x] gather.
//
// R5: exact PWL collapse -> 2048-bucket chord table per feature. Eval blocks
// stage their 4 features' tables (64KB) in SHARED memory; per-element gather is
// one LDS.64 (smem crossbar, ~3 cyc) instead of a 32-sector L2 gather.

#define BSZ   131072
#define NCOL  64
#define NF    48
#define H0N   40
#define H1N   20
#define PADN  1024            // padded exact-PWL table (max segments 861)

#define NB    2048
#define XMIN  (-6.0f)
#define XMAX  (6.0f)
#define WB    (12.0f / 2048.0f)       // 3/512, exact in fp32
#define SCALE (2048.0f / 12.0f)
#define INVW  (2048.0f / 12.0f)

#define TPB   256
#define RPT   8
#define ROWS_BLK (TPB * RPT)  // 2048 rows per eval block

#define F_INF  __int_as_float(0x7f800000)

__device__ float  g_bp[NF][PADN];    // sorted breakpoints, +INF padded (tail fallback)
__device__ float2 g_AC[NF][PADN];    // per-segment (A, C): f = A*x + C
__device__ float2 g_tab[NF][NB];     // per bucket: (y_left, chord_slope)

// ---------------------------------------------------------------------------
// Precompute scratch layout (dynamic smem)
// ---------------------------------------------------------------------------
struct PreScr {
    float sw0[H0N], sb0[H0N], sthr[H0N], ssthr[H0N];
    int   ssidx[H0N];
    float sW1[H0N * H1N];
    float sb1[H1N], sw2[H1N], sb2;
    float sak[41][H1N], sck[41][H1N];
    float crossZ[41][H1N];
    int   crossK[41][H1N];
    int   cnt[41], offs[42];
};

#define SB_OFF   0
#define SAC_OFF  4096
#define YV_OFF   12288                       // (NB+1)*4 = 8196 bytes
#define SCR_OFF  20488                       // 12288 + 8196 -> align 8
#define SMEM_PRE (SCR_OFF + sizeof(PreScr))

// ---------------------------------------------------------------------------
// Precompute: one block (256 thr) per feature. Phase A: exact PWL.
// Phase B: sample at NB+1 grid points (segment marching), emit chord table.
// ---------------------------------------------------------------------------
__global__ __launch_bounds__(256) void gam_precompute_kernel(
    const float* __restrict__ W0, const float* __restrict__ b0,
    const float* __restrict__ W1, const float* __restrict__ b1,
    const float* __restrict__ W2, const float* __restrict__ b2)
{
    extern __shared__ char smem[];
    float*  sB  = (float*)(smem + SB_OFF);     // [PADN]
    float2* sAC = (float2*)(smem + SAC_OFF);   // [PADN]
    float*  yv  = (float*)(smem + YV_OFF);     // [NB+1]
    PreScr* S   = (PreScr*)(smem + SCR_OFF);

    const int n = blockIdx.x;
    const int t = threadIdx.x;

    // ---- Phase A: exact PWL collapse ----
    for (int i = t; i < H0N * H1N; i += 256) S->sW1[i] = W1[n * H0N * H1N + i];
    if (t < H0N) {
        float w = W0[n * H0N + t];
        float b = b0[n * H0N + t];
        S->sw0[t] = w; S->sb0[t] = b;
        S->sthr[t] = (w != 0.0f) ? (-b / w) : ((b > 0.0f) ? -F_INF : F_INF);
    }
    if (t >= 64 && t < 64 + H1N) S->sb1[t - 64] = b1[n * H1N + (t - 64)];
    if (t >= 96 && t < 96 + H1N) S->sw2[t - 96] = W2[n * H1N + (t - 96)];
    if (t == 128) S->sb2 = b2[n];
    __syncthreads();

    if (t < H0N) {   // stable rank-sort of thresholds
        float v = S->sthr[t];
        int r = 0;
        for (int m = 0; m < H0N; m++) {
            float u = S->sthr[m];
            r += (u < v) || (u == v && m < t);
        }
        S->ssthr[r] = v;
        S->ssidx[r] = t;
    }
    __syncthreads();

    for (int idx = t; idx < 41 * H1N; idx += 256) {   // collapsed lines per interval
        const int i = idx / H1N;
        const int k = idx % H1N;
        float a = 0.0f, c = S->sb1[k];
        for (int r = 0; r < H0N; r++) {
            const int j = S->ssidx[r];
            const float w0 = S->sw0[j];
            const bool act = (w0 < 0.0f) ? (r >= i) : (r < i);
            if (act) {
                const float w1v = S->sW1[j * H1N + k];
                a = fmaf(w1v, w0, a);
                c = fmaf(w1v, S->sb0[j], c);
            }
        }
        S->sak[i][k] = a;
        S->sck[i][k] = c;
    }
    __syncthreads();

    if (t < 41) {    // interior zero crossings, sorted
        const int i = t;
        const float lo = (i == 0)  ? -F_INF : S->ssthr[i - 1];
        const float hi = (i == 40) ?  F_INF : S->ssthr[i];
        int c = 0;
        for (int k = 0; k < H1N; k++) {
            const float a = S->sak[i][k];
            if (a != 0.0f) {
                const float z = -S->sck[i][k] / a;
                if (z > lo && z < hi) {
                    int p = c++;
                    while (p > 0 && S->crossZ[i][p - 1] > z) {
                        S->crossZ[i][p] = S->crossZ[i][p - 1];
                        S->crossK[i][p] = S->crossK[i][p - 1];
                        p--;
                    }
                    S->crossZ[i][p] = z;
                    S->crossK[i][p] = k;
                }
            }
        }
        S->cnt[i] = c;
    }
    __syncthreads();

    if (t == 0) {
        int s = 0;
        for (int i = 0; i < 41; i++) { S->offs[i] = s; s += S->cnt[i] + 1; }
        S->offs[41] = s;
    }
    __syncthreads();
    const int total = S->offs[41];

    if (t < 41) {    // emit segments into smem
        const int i = t;
        const float lo = (i == 0) ? -F_INF : S->ssthr[i - 1];
        unsigned actm = 0;
        float A = 0.0f, C = S->sb2;
        for (int k = 0; k < H1N; k++) {
            const float a = S->sak[i][k], cc = S->sck[i][k];
            bool av;
            if (a == 0.0f)      av = (cc > 0.0f);
            else if (i == 0)    av = (a < 0.0f);
            else {
                const float v = fmaf(a, lo, cc);
                av = (v > 0.0f) || (v == 0.0f && a > 0.0f);
            }
            if (av) {
                actm |= (1u << k);
                A = fmaf(S->sw2[k], a,  A);
                C = fmaf(S->sw2[k], cc, C);
            }
        }
        const int base = S->offs[i];
        sAC[base] = make_float2(A, C);
        for (int s = 0; s < S->cnt[i]; s++) {
            sB[base + s] = S->crossZ[i][s];
            const int k = S->crossK[i][s];
            const float sgn = (actm >> k) & 1u ? -1.0f : 1.0f;
            actm ^= (1u << k);
            A = fmaf(sgn * S->sw2[k], S->sak[i][k], A);
            C = fmaf(sgn * S->sw2[k], S->sck[i][k], C);
            sAC[base + s + 1] = make_float2(A, C);
        }
        if (i < 40) sB[base + S->cnt[i]] = S->ssthr[i];
    }
    __syncthreads();

    for (int j = total - 1 + t; j < PADN; j += 256) sB[j] = F_INF;
    __syncthreads();

    // export exact PWL for the tail fallback
    for (int j = t; j < PADN; j += 256) {
        g_bp[n][j] = sB[j];
        g_AC[n][j] = (j < total) ? sAC[j] : make_float2(0.0f, 0.0f);
    }

    // ---- Phase B: sample f at NB+1 grid points (segment marching) ----
    {
        const int per = (NB + 1 + 255) / 256;   // 9 points per thread
        const int i0 = t * per;
        const int i1 = min(i0 + per, NB + 1);
        if (i0 < i1) {
            float x0 = fmaf((float)i0, WB, XMIN);
            int p = 0;
            #pragma unroll
            for (int s = 512; s >= 1; s >>= 1)
                if (sB[p + s - 1] < x0) p += s;
            for (int i = i0; i < i1; i++) {
                const float x = fmaf((float)i, WB, XMIN);
                while (sB[p] < x) p++;
                const float2 ac = sAC[p];
                yv[i] = fmaf(ac.x, x, ac.y);
            }
        }
    }
    __syncthreads();

    for (int b = t; b < NB; b += 256)
        g_tab[n][b] = make_float2(yv[b], (yv[b + 1] - yv[b]) * INVW);
}

// ---------------------------------------------------------------------------
// Eval (fused num + cat). Block = 2048 rows x 4 columns.
// Numeric blocks stage 4 x 2048 x float2 (64KB) chord tables in smem.
// ---------------------------------------------------------------------------
#define SMEM_EVAL (4 * NB * sizeof(float2))   // 65536

__global__ __launch_bounds__(TPB) void gam_eval_kernel(
    const float* __restrict__ in,
    const float* __restrict__ cb,
    float* __restrict__ out)
{
    extern __shared__ char smem[];
    const int g   = blockIdx.y;
    const int tid = threadIdx.x;
    const int rbase = blockIdx.x * ROWS_BLK + tid;

    if (g < 12) {
        float2* sTab = (float2*)smem;          // [4*NB], features g*4..g*4+3
        {
            const float4* src = reinterpret_cast<const float4*>(&g_tab[g * 4][0]);
            float4* dst = reinterpret_cast<float4*>(sTab);
            for (int i = tid; i < 4 * NB / 2; i += TPB) dst[i] = src[i];
        }
        __syncthreads();

        #pragma unroll
        for (int e = 0; e < RPT; e++) {
            const int row = rbase + e * TPB;
            const float4 v = *reinterpret_cast<const float4*>(in + row * NCOL + g * 4);
            const float xs[4] = {v.x, v.y, v.z, v.w};
            float os[4];
            #pragma unroll
            for (int f = 0; f < 4; f++) {
                const float x = xs[f];
                float r;
                if (x >= XMIN && x <= XMAX) {
                    int b = (int)((x - XMIN) * SCALE);
                    b = min(b, NB - 1);
                    const float2 ys = sTab[f * NB + b];
                    const float xL = fmaf((float)b, WB, XMIN);
                    r = fmaf(ys.y, x - xL, ys.x);
                } else {
                    // exact PWL fallback (|x| > 6: ~never)
                    const int n = g * 4 + f;
                    int p = 0;
                    #pragma unroll
                    for (int s = 512; s >= 1; s >>= 1)
                        if (g_bp[n][p + s - 1] < x) p += s;
                    const float2 ac = g_AC[n][p];
                    r = fmaf(ac.x, x, ac.y);
                }
                os[f] = r;
            }
            *reinterpret_cast<float4*>(out + row * NCOL + g * 4) =
                make_float4(os[0], os[1], os[2], os[3]);
        }
    } else {
        float* scb = (float*)smem;             // [16*32]
        for (int i = tid; i < 16 * 32; i += TPB) scb[i] = cb[i];
        __syncthreads();

        const int cbase = (g - 12) * 4;
        #pragma unroll
        for (int e = 0; e < RPT; e++) {
            const int row = rbase + e * TPB;
            const float4 v = *reinterpret_cast<const float4*>(in + row * NCOL + g * 4);
            float4 o;
            o.x = scb[(cbase + 0) * 32 + (int)v.x];
            o.y = scb[(cbase + 1) * 32 + (int)v.y];
            o.z = scb[(cbase + 2) * 32 + (int)v.z];
            o.w = scb[(cbase + 3) * 32 + (int)v.w];
            *reinterpret_cast<float4*>(out + row * NCOL + g * 4) = o;
        }
    }
}

extern "C" void kernel_launch(void* const* d_in, const int* in_sizes, int n_in,
                              void* d_out, int out_size)
{
    const float* in = (const float*)d_in[0];
    const float* W0 = (const float*)d_in[1];
    const float* b0 = (const float*)d_in[2];
    const float* W1 = (const float*)d_in[3];
    const float* b1 = (const float*)d_in[4];
    const float* W2 = (const float*)d_in[5];
    const float* b2 = (const float*)d_in[6];
    const float* cb = (const float*)d_in[7];
    float* out = (float*)d_out;

    static bool attr_done = false;
    if (!attr_done) {
        cudaFuncSetAttribute(gam_precompute_kernel,
                             cudaFuncAttributeMaxDynamicSharedMemorySize,
                             (int)SMEM_PRE);
        cudaFuncSetAttribute(gam_eval_kernel,
                             cudaFuncAttributeMaxDynamicSharedMemorySize,
                             (int)SMEM_EVAL);
        attr_done = true;
    }

    gam_precompute_kernel<<<NF, 256, SMEM_PRE>>>(W0, b0, W1, b1, W2, b2);

    dim3 grid(BSZ / ROWS_BLK, 16, 1);   // 64 x 16
    gam_eval_kernel<<<grid, TPB, SMEM_EVAL>>>(in, cb, out);
}

// round 6
// speedup vs baseline: 2.6083x; 2.2053x over previous
#include <cuda_runtime.h>
#include <math.h>

// pyGAMNet on GB300.
// Cols 0..47: per-feature scalar MLP 1->40->20->1 (ReLU)  == scalar function f_n(x).
// Cols 48..63: class_bias[c, (int)x] gather.
//
// R6: per-feature 512-bucket chord table over [-6,6], built by DIRECT MLP
// sampling (513 grid points/feature). Eval: one persistent 1024-thread block
// per SM holds ALL 48 tables (~193KB smem) + cat table; rows are processed
// fully coalesced (warp = 2 contiguous rows). Gather = 1 LDS.64.
// |x|>6 fallback: exact direct MLP eval (predicated, ~never taken).

#define BSZ   131072
#define NCOL  64
#define NF    48
#define H0N   40
#define H1N   20

#define NB    512
#define NBP   514                     // padded stride: de-skews bank alignment
#define XMIN  (-6.0f)
#define XMAX  (6.0f)
#define WB    (12.0f / 512.0f)        // 3/128, exact in fp32
#define SCALE (512.0f / 12.0f)
#define INVW  (512.0f / 12.0f)

#define EVAL_TPB   1024
#define EVAL_GRID  148
#define ROWS_PB    ((BSZ + EVAL_GRID - 1) / EVAL_GRID)   // 886

__device__ float2 g_tab[NF][NB];      // per bucket: (y_left, chord_slope)

// ---------------------------------------------------------------------------
// Exact fallback: full MLP eval for one (feature, x). ~Never executed.
// ---------------------------------------------------------------------------
__device__ __noinline__ float mlp_exact(
    int n, float x,
    const float* __restrict__ W0, const float* __restrict__ b0,
    const float* __restrict__ W1, const float* __restrict__ b1,
    const float* __restrict__ W2, const float* __restrict__ b2)
{
    float acc[H1N];
    for (int k = 0; k < H1N; k++) acc[k] = b1[n * H1N + k];
    for (int j = 0; j < H0N; j++) {
        const float h0 = fmaxf(fmaf(x, W0[n * H0N + j], b0[n * H0N + j]), 0.0f);
        const float* w1r = &W1[(n * H0N + j) * H1N];
        for (int k = 0; k < H1N; k++) acc[k] = fmaf(w1r[k], h0, acc[k]);
    }
    float o = b2[n];
    for (int k = 0; k < H1N; k++) o = fmaf(fmaxf(acc[k], 0.0f), W2[n * H1N + k], o);
    return o;
}

// ---------------------------------------------------------------------------
// Precompute: one block per feature. Sample MLP at 513 grid points -> chords.
// ---------------------------------------------------------------------------
__global__ __launch_bounds__(256) void gam_precompute_kernel(
    const float* __restrict__ W0, const float* __restrict__ b0,
    const float* __restrict__ W1, const float* __restrict__ b1,
    const float* __restrict__ W2, const float* __restrict__ b2)
{
    __shared__ float sw0[H0N], sb0[H0N];
    __shared__ float sW1[H0N * H1N];
    __shared__ float sb1[H1N], sw2[H1N];
    __shared__ float sb2;
    __shared__ float yv[NB + 1];

    const int n = blockIdx.x;
    const int t = threadIdx.x;

    for (int i = t; i < H0N * H1N; i += 256) sW1[i] = W1[n * H0N * H1N + i];
    if (t < H0N) {
        sw0[t] = W0[n * H0N + t];
        sb0[t] = b0[n * H0N + t];
    }
    if (t >= 64 && t < 64 + H1N) sb1[t - 64] = b1[n * H1N + (t - 64)];
    if (t >= 96 && t < 96 + H1N) sw2[t - 96] = W2[n * H1N + (t - 96)];
    if (t == 128) sb2 = b2[n];
    __syncthreads();

    for (int i = t; i < NB + 1; i += 256) {
        const float x = fmaf((float)i, WB, XMIN);    // exact grid point
        float acc[H1N];
        #pragma unroll
        for (int k = 0; k < H1N; k++) acc[k] = sb1[k];
        #pragma unroll 4
        for (int j = 0; j < H0N; j++) {
            const float h0 = fmaxf(fmaf(x, sw0[j], sb0[j]), 0.0f);
            const float* w1r = &sW1[j * H1N];
            #pragma unroll
            for (int k = 0; k < H1N; k++) acc[k] = fmaf(w1r[k], h0, acc[k]);
        }
        float o = sb2;
        #pragma unroll
        for (int k = 0; k < H1N; k++) o = fmaf(fmaxf(acc[k], 0.0f), sw2[k], o);
        yv[i] = o;
    }
    __syncthreads();

    for (int bidx = t; bidx < NB; bidx += 256)
        g_tab[n][bidx] = make_float2(yv[bidx], (yv[bidx + 1] - yv[bidx]) * INVW);
}

// ---------------------------------------------------------------------------
// Eval: 148 persistent blocks x 1024 threads. All tables in smem.
// Thread -> (row = r0 + tid/16, quad q = tid%16): handles cols 4q..4q+3.
// Warp covers 2 contiguous rows -> fully coalesced 128B I/O.
// ---------------------------------------------------------------------------
#define TAB_FLOATS (NF * NBP * 2)                       // float2 as 2 floats
#define SMEM_EVAL  ((TAB_FLOATS + 16 * 32) * 4)         // ~199.4 KB

__global__ __launch_bounds__(EVAL_TPB, 1) void gam_eval_kernel(
    const float* __restrict__ in,
    const float* __restrict__ cb,
    const float* __restrict__ W0, const float* __restrict__ b0,
    const float* __restrict__ W1, const float* __restrict__ b1,
    const float* __restrict__ W2, const float* __restrict__ b2,
    float* __restrict__ out)
{
    extern __shared__ float smem[];
    float2* sTab = (float2*)smem;                 // [n*NBP + b]
    float*  scb  = smem + TAB_FLOATS;             // [16*32]

    const int tid = threadIdx.x;

    // stage all 48 chord tables (dense global -> padded smem stride)
    for (int i = tid; i < NF * NB; i += EVAL_TPB) {
        const int n = i >> 9;           // /NB
        const int b = i & (NB - 1);
        sTab[n * NBP + b] = g_tab[n][b];
    }
    for (int i = tid; i < 16 * 32; i += EVAL_TPB) scb[i] = cb[i];
    __syncthreads();

    const int start = blockIdx.x * ROWS_PB;
    const int rend  = min(start + ROWS_PB, BSZ);

    const int q    = tid & 15;          // quad 0..15 (cols 4q..4q+3)
    const int rrel = tid >> 4;          // 0..63

    for (int r0 = start; r0 < rend; r0 += 64) {
        const int row = r0 + rrel;
        if (row >= rend) break;

        const float4 v = *reinterpret_cast<const float4*>(in + row * NCOL + q * 4);
        float4 o;

        if (q < 12) {
            const float xs[4] = {v.x, v.y, v.z, v.w};
            float os[4];
            #pragma unroll
            for (int f = 0; f < 4; f++) {
                const int n = q * 4 + f;
                const float x = xs[f];
                float r;
                if (x >= XMIN && x <= XMAX) {
                    int b = (int)((x - XMIN) * SCALE);
                    b = min(b, NB - 1);
                    const float2 ys = sTab[n * NBP + b];
                    const float xL = fmaf((float)b, WB, XMIN);
                    r = fmaf(ys.y, x - xL, ys.x);
                } else {
                    r = mlp_exact(n, x, W0, b0, W1, b1, W2, b2);
                }
                os[f] = r;
            }
            o = make_float4(os[0], os[1], os[2], os[3]);
        } else {
            const int cbase = (q - 12) * 4;
            o.x = scb[(cbase + 0) * 32 + (int)v.x];
            o.y = scb[(cbase + 1) * 32 + (int)v.y];
            o.z = scb[(cbase + 2) * 32 + (int)v.z];
            o.w = scb[(cbase + 3) * 32 + (int)v.w];
        }

        *reinterpret_cast<float4*>(out + row * NCOL + q * 4) = o;
    }
}

extern "C" void kernel_launch(void* const* d_in, const int* in_sizes, int n_in,
                              void* d_out, int out_size)
{
    const float* in = (const float*)d_in[0];
    const float* W0 = (const float*)d_in[1];
    const float* b0 = (const float*)d_in[2];
    const float* W1 = (const float*)d_in[3];
    const float* b1 = (const float*)d_in[4];
    const float* W2 = (const float*)d_in[5];
    const float* b2 = (const float*)d_in[6];
    const float* cb = (const float*)d_in[7];
    float* out = (float*)d_out;

    static bool attr_done = false;
    if (!attr_done) {
        cudaFuncSetAttribute(gam_eval_kernel,
                             cudaFuncAttributeMaxDynamicSharedMemorySize,
                             (int)SMEM_EVAL);
        attr_done = true;
    }

    gam_precompute_kernel<<<NF, 256>>>(W0, b0, W1, b1, W2, b2);

    gam_eval_kernel<<<EVAL_GRID, EVAL_TPB, SMEM_EVAL>>>(
        in, cb, W0, b0, W1, b1, W2, b2, out);
}

// round 7
// speedup vs baseline: 2.6149x; 1.0025x over previous
#include <cuda_runtime.h>
#include <math.h>

// pyGAMNet on GB300.
// Cols 0..47: per-feature scalar MLP 1->40->20->1 (ReLU)  == scalar function f_n(x).
// Cols 48..63: class_bias[c, (int)x] gather.
//
// R7: 512-bucket line table (m,c) per feature over [-6,6], built by direct MLP
// sampling. Eval: 148 persistent 1024-thread blocks, ALL tables in smem with a
// per-quad [q][b][f] layout (region stride 4098 floats == 2 mod 32) so the 12
// lanes of each gather LDS hit 12 distinct banks. r = fma(m, x, c).

#define BSZ   131072
#define NCOL  64
#define NF    48
#define H0N   40
#define H1N   20

#define NB    512
#define XMIN  (-6.0f)
#define XMAX  (6.0f)
#define WB    (12.0f / 512.0f)        // 3/128, exact in fp32
#define SCALE (512.0f / 12.0f)
#define INVW  (512.0f / 12.0f)

#define EVAL_TPB   1024
#define EVAL_GRID  148
#define ROWS_PB    ((BSZ + EVAL_GRID - 1) / EVAL_GRID)   // 886

// smem layout (eval): 12 quad-regions of (NB*4 + 1) float2  (stride 4098 floats)
#define REG_F2     (NB * 4 + 1)                   // 2049 float2 per region
#define TAB_F2     (12 * REG_F2)                  // 24588 float2
#define SMEM_EVAL  ((TAB_F2 * 2 + 16 * 32) * 4)   // ~198.8 KB

__device__ float2 g_tab[NF][NB];      // per bucket: (slope m, intercept c)

// ---------------------------------------------------------------------------
// Exact fallback: full MLP eval for one (feature, x). ~Never executed.
// ---------------------------------------------------------------------------
__device__ __noinline__ float mlp_exact(
    int n, float x,
    const float* __restrict__ W0, const float* __restrict__ b0,
    const float* __restrict__ W1, const float* __restrict__ b1,
    const float* __restrict__ W2, const float* __restrict__ b2)
{
    float acc[H1N];
    for (int k = 0; k < H1N; k++) acc[k] = b1[n * H1N + k];
    for (int j = 0; j < H0N; j++) {
        const float h0 = fmaxf(fmaf(x, W0[n * H0N + j], b0[n * H0N + j]), 0.0f);
        const float* w1r = &W1[(n * H0N + j) * H1N];
        for (int k = 0; k < H1N; k++) acc[k] = fmaf(w1r[k], h0, acc[k]);
    }
    float o = b2[n];
    for (int k = 0; k < H1N; k++) o = fmaf(fmaxf(acc[k], 0.0f), W2[n * H1N + k], o);
    return o;
}

// ---------------------------------------------------------------------------
// Precompute: grid (48, 2). Block (n, chunk) samples 257 grid points and emits
// 256 buckets as (m, c) lines: f(x) ~ m*x + c on the bucket.
// ---------------------------------------------------------------------------
__global__ __launch_bounds__(256) void gam_precompute_kernel(
    const float* __restrict__ W0, const float* __restrict__ b0,
    const float* __restrict__ W1, const float* __restrict__ b1,
    const float* __restrict__ W2, const float* __restrict__ b2)
{
    __shared__ float sw0[H0N], sb0[H0N];
    __shared__ float sW1[H0N * H1N];
    __shared__ float sb1[H1N], sw2[H1N];
    __shared__ float sb2;
    __shared__ float yv[257];

    const int n  = blockIdx.x;
    const int p0 = blockIdx.y * 256;          // first grid point of this chunk
    const int t  = threadIdx.x;

    for (int i = t; i < H0N * H1N; i += 256) sW1[i] = W1[n * H0N * H1N + i];
    if (t < H0N) {
        sw0[t] = W0[n * H0N + t];
        sb0[t] = b0[n * H0N + t];
    }
    if (t >= 64 && t < 64 + H1N) sb1[t - 64] = b1[n * H1N + (t - 64)];
    if (t >= 96 && t < 96 + H1N) sw2[t - 96] = W2[n * H1N + (t - 96)];
    if (t == 128) sb2 = b2[n];
    __syncthreads();

    for (int i = t; i < 257; i += 256) {
        const float x = fmaf((float)(p0 + i), WB, XMIN);   // exact grid point
        float acc[H1N];
        #pragma unroll
        for (int k = 0; k < H1N; k++) acc[k] = sb1[k];
        #pragma unroll 4
        for (int j = 0; j < H0N; j++) {
            const float h0 = fmaxf(fmaf(x, sw0[j], sb0[j]), 0.0f);
            const float* w1r = &sW1[j * H1N];
            #pragma unroll
            for (int k = 0; k < H1N; k++) acc[k] = fmaf(w1r[k], h0, acc[k]);
        }
        float o = sb2;
        #pragma unroll
        for (int k = 0; k < H1N; k++) o = fmaf(fmaxf(acc[k], 0.0f), sw2[k], o);
        yv[i] = o;
    }
    __syncthreads();

    // buckets p0..p0+255: m = (y1-y0)/w, c = y0 - m*xL
    {
        const int b = p0 + t;
        const float m  = (yv[t + 1] - yv[t]) * INVW;
        const float xL = fmaf((float)b, WB, XMIN);
        const float c  = fmaf(-m, xL, yv[t]);
        g_tab[n][b] = make_float2(m, c);
    }
}

// ---------------------------------------------------------------------------
// Eval: 148 persistent blocks x 1024 threads.
// Thread -> (row = r0 + tid/16, quad q = tid%16): handles cols 4q..4q+3.
// Numeric tables in smem, layout float2 idx = q*REG_F2 + b*4 + f.
// ---------------------------------------------------------------------------
__global__ __launch_bounds__(EVAL_TPB, 1) void gam_eval_kernel(
    const float* __restrict__ in,
    const float* __restrict__ cb,
    const float* __restrict__ W0, const float* __restrict__ b0,
    const float* __restrict__ W1, const float* __restrict__ b1,
    const float* __restrict__ W2, const float* __restrict__ b2,
    float* __restrict__ out)
{
    extern __shared__ float smem[];
    float2* sTab = (float2*)smem;                 // [TAB_F2]
    float*  scb  = smem + TAB_F2 * 2;             // [16*32]

    const int tid = threadIdx.x;

    // stage tables: g_tab[n][b] -> sTab[(n>>2)*REG_F2 + b*4 + (n&3)]
    for (int i = tid; i < NF * NB; i += EVAL_TPB) {
        const int n = i >> 9;            // /NB
        const int b = i & (NB - 1);
        sTab[(n >> 2) * REG_F2 + b * 4 + (n & 3)] = g_tab[n][b];
    }
    for (int i = tid; i < 16 * 32; i += EVAL_TPB) scb[i] = cb[i];
    __syncthreads();

    const int start = blockIdx.x * ROWS_PB;
    const int rend  = min(start + ROWS_PB, BSZ);

    const int q    = tid & 15;           // quad 0..15 (cols 4q..4q+3)
    const int rrel = tid >> 4;           // 0..63
    const float2* qbase = sTab + q * REG_F2;     // hoisted region base
    const int cbase = (q - 12) * 4;

    // guard-free full tiles, then tail
    int r0 = start;
    #pragma unroll 2
    for (; r0 + 64 <= rend; r0 += 64) {
        const int row = r0 + rrel;
        const float4 v = *reinterpret_cast<const float4*>(in + row * NCOL + q * 4);
        float4 o;
        if (q < 12) {
            const float xs[4] = {v.x, v.y, v.z, v.w};
            float os[4];
            #pragma unroll
            for (int f = 0; f < 4; f++) {
                const float x = xs[f];
                float r;
                if (fabsf(x) <= XMAX) {
                    int b = (int)((x - XMIN) * SCALE);
                    b = min(b, NB - 1);
                    const float2 mc = qbase[b * 4 + f];
                    r = fmaf(mc.x, x, mc.y);
                } else {
                    r = mlp_exact(q * 4 + f, x, W0, b0, W1, b1, W2, b2);
                }
                os[f] = r;
            }
            o = make_float4(os[0], os[1], os[2], os[3]);
        } else {
            o.x = scb[(cbase + 0) * 32 + (int)v.x];
            o.y = scb[(cbase + 1) * 32 + (int)v.y];
            o.z = scb[(cbase + 2) * 32 + (int)v.z];
            o.w = scb[(cbase + 3) * 32 + (int)v.w];
        }
        *reinterpret_cast<float4*>(out + row * NCOL + q * 4) = o;
    }
    // tail
    {
        const int row = r0 + rrel;
        if (row < rend) {
            const float4 v = *reinterpret_cast<const float4*>(in + row * NCOL + q * 4);
            float4 o;
            if (q < 12) {
                const float xs[4] = {v.x, v.y, v.z, v.w};
                float os[4];
                #pragma unroll
                for (int f = 0; f < 4; f++) {
                    const float x = xs[f];
                    float r;
                    if (fabsf(x) <= XMAX) {
                        int b = (int)((x - XMIN) * SCALE);
                        b = min(b, NB - 1);
                        const float2 mc = qbase[b * 4 + f];
                        r = fmaf(mc.x, x, mc.y);
                    } else {
                        r = mlp_exact(q * 4 + f, x, W0, b0, W1, b1, W2, b2);
                    }
                    os[f] = r;
                }
                o = make_float4(os[0], os[1], os[2], os[3]);
            } else {
                o.x = scb[(cbase + 0) * 32 + (int)v.x];
                o.y = scb[(cbase + 1) * 32 + (int)v.y];
                o.z = scb[(cbase + 2) * 32 + (int)v.z];
                o.w = scb[(cbase + 3) * 32 + (int)v.w];
            }
            *reinterpret_cast<float4*>(out + row * NCOL + q * 4) = o;
        }
    }
}

extern "C" void kernel_launch(void* const* d_in, const int* in_sizes, int n_in,
                              void* d_out, int out_size)
{
    const float* in = (const float*)d_in[0];
    const float* W0 = (const float*)d_in[1];
    const float* b0 = (const float*)d_in[2];
    const float* W1 = (const float*)d_in[3];
    const float* b1 = (const float*)d_in[4];
    const float* W2 = (const float*)d_in[5];
    const float* b2 = (const float*)d_in[6];
    const float* cb = (const float*)d_in[7];
    float* out = (float*)d_out;

    static bool attr_done = false;
    if (!attr_done) {
        cudaFuncSetAttribute(gam_eval_kernel,
                             cudaFuncAttributeMaxDynamicSharedMemorySize,
                             (int)SMEM_EVAL);
        attr_done = true;
    }

    dim3 pgrid(NF, 2, 1);
    gam_precompute_kernel<<<pgrid, 256>>>(W0, b0, W1, b1, W2, b2);

    gam_eval_kernel<<<EVAL_GRID, EVAL_TPB, SMEM_EVAL>>>(
        in, cb, W0, b0, W1, b1, W2, b2, out);
}

// round 8
// speedup vs baseline: 2.8764x; 1.1000x over previous
#include <cuda_runtime.h>
#include <math.h>

// pyGAMNet on GB300.
// Cols 0..47: per-feature scalar MLP 1->40->20->1 (ReLU)  == scalar function f_n(x).
// Cols 48..63: class_bias[c, (int)x] gather.
//
// R8: ALL 64 columns evaluated by ONE branch-free table path:
//   b = (int)fma(x, scale_q, off_q); b = min(b, nbm1_q);
//   (m,c) = qbase_q[4b+f];  r = fma(m, x, c)
// Numeric quads: 512-bucket chord-line tables over [-6,6] (direct MLP sampling).
// Cat quads: 32-bucket tables with m=0, c=class_bias (scale=1).
// Rare |x|>6 fallback: one uniform branch per float4 -> exact MLP eval.

#define BSZ   131072
#define NCOL  64
#define NF    48
#define H0N   40
#define H1N   20

#define NB    512
#define XMIN  (-6.0f)
#define XMAX  (6.0f)
#define WB    (12.0f / 512.0f)        // 3/128, exact in fp32
#define SCALE (512.0f / 12.0f)
#define INVW  (512.0f / 12.0f)

#define EVAL_TPB   1024
#define EVAL_GRID  148
#define ROWS_PB    ((BSZ + EVAL_GRID - 1) / EVAL_GRID)   // 886

// smem: 12 numeric regions of (NB*4+1) float2, then 4 cat regions of (32*4+1)
#define REG_F2     (NB * 4 + 1)                   // 2049
#define CAT_REG    (32 * 4 + 1)                   // 129
#define CAT_OFF    (12 * REG_F2)                  // 24588
#define TAB_F2     (CAT_OFF + 4 * CAT_REG)        // 25104
#define SMEM_EVAL  (TAB_F2 * 8)                   // 200832 B

__device__ float2 g_tab[NF][NB];      // per bucket: (slope m, intercept c)

// ---------------------------------------------------------------------------
// Exact fallback: full MLP eval for one (feature, x). ~Never executed.
// ---------------------------------------------------------------------------
__device__ __noinline__ float mlp_exact(
    int n, float x,
    const float* __restrict__ W0, const float* __restrict__ b0,
    const float* __restrict__ W1, const float* __restrict__ b1,
    const float* __restrict__ W2, const float* __restrict__ b2)
{
    float acc[H1N];
    for (int k = 0; k < H1N; k++) acc[k] = b1[n * H1N + k];
    for (int j = 0; j < H0N; j++) {
        const float h0 = fmaxf(fmaf(x, W0[n * H0N + j], b0[n * H0N + j]), 0.0f);
        const float* w1r = &W1[(n * H0N + j) * H1N];
        for (int k = 0; k < H1N; k++) acc[k] = fmaf(w1r[k], h0, acc[k]);
    }
    float o = b2[n];
    for (int k = 0; k < H1N; k++) o = fmaf(fmaxf(acc[k], 0.0f), W2[n * H1N + k], o);
    return o;
}

// ---------------------------------------------------------------------------
// Precompute: grid (48, 2). Block (n, chunk) samples 257 grid points and emits
// 256 buckets as (m, c) lines: f(x) ~ m*x + c on the bucket.
// ---------------------------------------------------------------------------
__global__ __launch_bounds__(256) void gam_precompute_kernel(
    const float* __restrict__ W0, const float* __restrict__ b0,
    const float* __restrict__ W1, const float* __restrict__ b1,
    const float* __restrict__ W2, const float* __restrict__ b2)
{
    __shared__ float sw0[H0N], sb0[H0N];
    __shared__ float sW1[H0N * H1N];
    __shared__ float sb1[H1N], sw2[H1N];
    __shared__ float sb2;
    __shared__ float yv[257];

    const int n  = blockIdx.x;
    const int p0 = blockIdx.y * 256;
    const int t  = threadIdx.x;

    for (int i = t; i < H0N * H1N; i += 256) sW1[i] = W1[n * H0N * H1N + i];
    if (t < H0N) {
        sw0[t] = W0[n * H0N + t];
        sb0[t] = b0[n * H0N + t];
    }
    if (t >= 64 && t < 64 + H1N) sb1[t - 64] = b1[n * H1N + (t - 64)];
    if (t >= 96 && t < 96 + H1N) sw2[t - 96] = W2[n * H1N + (t - 96)];
    if (t == 128) sb2 = b2[n];
    __syncthreads();

    for (int i = t; i < 257; i += 256) {
        const float x = fmaf((float)(p0 + i), WB, XMIN);   // exact grid point
        float acc[H1N];
        #pragma unroll
        for (int k = 0; k < H1N; k++) acc[k] = sb1[k];
        #pragma unroll 4
        for (int j = 0; j < H0N; j++) {
            const float h0 = fmaxf(fmaf(x, sw0[j], sb0[j]), 0.0f);
            const float* w1r = &sW1[j * H1N];
            #pragma unroll
            for (int k = 0; k < H1N; k++) acc[k] = fmaf(w1r[k], h0, acc[k]);
        }
        float o = sb2;
        #pragma unroll
        for (int k = 0; k < H1N; k++) o = fmaf(fmaxf(acc[k], 0.0f), sw2[k], o);
        yv[i] = o;
    }
    __syncthreads();

    {
        const int b = p0 + t;
        const float m  = (yv[t + 1] - yv[t]) * INVW;
        const float xL = fmaf((float)b, WB, XMIN);
        const float c  = fmaf(-m, xL, yv[t]);
        g_tab[n][b] = make_float2(m, c);
    }
}

// ---------------------------------------------------------------------------
// Eval: 148 persistent blocks x 1024 threads. Uniform table path for all cols.
// Thread -> (row = r0 + tid/16, quad q = tid%16): handles cols 4q..4q+3.
// ---------------------------------------------------------------------------
struct QCtx {
    const float2* qbase;
    float scale, off, bound;
    int nbm1, q;
};

__device__ __forceinline__ void eval_quad(
    const QCtx& ctx, const float4 v, float4& o,
    const float* __restrict__ W0, const float* __restrict__ b0,
    const float* __restrict__ W1, const float* __restrict__ b1,
    const float* __restrict__ W2, const float* __restrict__ b2)
{
    const float xs[4] = {v.x, v.y, v.z, v.w};
    float os[4];
    bool bad = false;
    #pragma unroll
    for (int f = 0; f < 4; f++) {
        const float x = xs[f];
        int b = (int)fmaf(x, ctx.scale, ctx.off);
        b = min(b, ctx.nbm1);
        const float2 mc = ctx.qbase[b * 4 + f];
        os[f] = fmaf(mc.x, x, mc.y);
        bad |= (fabsf(x) > ctx.bound);
    }
    if (__builtin_expect(bad, 0)) {   // numeric |x|>6: ~never
        #pragma unroll
        for (int f = 0; f < 4; f++)
            if (fabsf(xs[f]) > ctx.bound)
                os[f] = mlp_exact(ctx.q * 4 + f, xs[f], W0, b0, W1, b1, W2, b2);
    }
    o = make_float4(os[0], os[1], os[2], os[3]);
}

__global__ __launch_bounds__(EVAL_TPB, 1) void gam_eval_kernel(
    const float* __restrict__ in,
    const float* __restrict__ cb,
    const float* __restrict__ W0, const float* __restrict__ b0,
    const float* __restrict__ W1, const float* __restrict__ b1,
    const float* __restrict__ W2, const float* __restrict__ b2,
    float* __restrict__ out)
{
    extern __shared__ float smem[];
    float2* sTab = (float2*)smem;     // [TAB_F2]

    const int tid = threadIdx.x;

    // numeric tables: g_tab[n][b] -> sTab[(n>>2)*REG_F2 + b*4 + (n&3)]
    for (int i = tid; i < NF * NB; i += EVAL_TPB) {
        const int n = i >> 9;
        const int b = i & (NB - 1);
        sTab[(n >> 2) * REG_F2 + b * 4 + (n & 3)] = g_tab[n][b];
    }
    // cat tables: cb[c*32+x] -> (m=0, c=bias) in region 12+(c>>2)
    for (int i = tid; i < 16 * 32; i += EVAL_TPB) {
        const int c = i >> 5;
        const int x = i & 31;
        sTab[CAT_OFF + (c >> 2) * CAT_REG + x * 4 + (c & 3)] =
            make_float2(0.0f, cb[i]);
    }
    __syncthreads();

    const int start = blockIdx.x * ROWS_PB;
    const int rend  = min(start + ROWS_PB, BSZ);

    const int q    = tid & 15;
    const int rrel = tid >> 4;
    const bool isnum = (q < 12);

    QCtx ctx;
    ctx.q     = q;
    ctx.qbase = isnum ? (sTab + q * REG_F2)
                      : (sTab + CAT_OFF + (q - 12) * CAT_REG);
    ctx.scale = isnum ? SCALE : 1.0f;
    ctx.off   = isnum ? 256.0f : 0.0f;     // 6 * 512/12 = 256 exact
    ctx.bound = isnum ? XMAX : 1e30f;
    ctx.nbm1  = isnum ? (NB - 1) : 31;

    int r0 = start;
    #pragma unroll 2
    for (; r0 + 64 <= rend; r0 += 64) {
        const int row = r0 + rrel;
        const float4 v = *reinterpret_cast<const float4*>(in + row * NCOL + q * 4);
        float4 o;
        eval_quad(ctx, v, o, W0, b0, W1, b1, W2, b2);
        *reinterpret_cast<float4*>(out + row * NCOL + q * 4) = o;
    }
    {   // tail (< 64 rows)
        const int row = r0 + rrel;
        if (row < rend) {
            const float4 v = *reinterpret_cast<const float4*>(in + row * NCOL + q * 4);
            float4 o;
            eval_quad(ctx, v, o, W0, b0, W1, b1, W2, b2);
            *reinterpret_cast<float4*>(out + row * NCOL + q * 4) = o;
        }
    }
}

extern "C" void kernel_launch(void* const* d_in, const int* in_sizes, int n_in,
                              void* d_out, int out_size)
{
    const float* in = (const float*)d_in[0];
    const float* W0 = (const float*)d_in[1];
    const float* b0 = (const float*)d_in[2];
    const float* W1 = (const float*)d_in[3];
    const float* b1 = (const float*)d_in[4];
    const float* W2 = (const float*)d_in[5];
    const float* b2 = (const float*)d_in[6];
    const float* cb = (const float*)d_in[7];
    float* out = (float*)d_out;

    static bool attr_done = false;
    if (!attr_done) {
        cudaFuncSetAttribute(gam_eval_kernel,
                             cudaFuncAttributeMaxDynamicSharedMemorySize,
                             (int)SMEM_EVAL);
        attr_done = true;
    }

    dim3 pgrid(NF, 2, 1);
    gam_precompute_kernel<<<pgrid, 256>>>(W0, b0, W1, b1, W2, b2);

    gam_eval_kernel<<<EVAL_GRID, EVAL_TPB, SMEM_EVAL>>>(
        in, cb, W0, b0, W1, b1, W2, b2, out);
}